// round 3
// baseline (speedup 1.0000x reference)
#include <cuda_runtime.h>
#include <cuda_bf16.h>

#define FULL 0xFFFFFFFFu

__constant__ float cW1[20 * 64];
__constant__ float cb1[64];
__constant__ float cW2[64];
__constant__ float cb2[1];

__device__ __forceinline__ void ce(float& a, float& b) {
    float hi = fmaxf(a, b);
    float lo = fminf(a, b);
    a = hi; b = lo;
}

// Each warp owns 32 consecutive rows.
// Phase A (per row, warp-parallel): softmax->top4 stats -> shared (20 floats/row)
// Phase B (lane r = local row r): MLP with inline-constant weights -> q per lane
// Phase C (per row): out[80] = scores[80] + q
#define SST 28  // floats per row in stat smem (16B-aligned quads, conflict-free LDS.128)

__global__ __launch_bounds__(256)
void lqe_kernel(const float* __restrict__ scores,
                const float* __restrict__ corners,
                float* __restrict__ out,
                int rows)
{
    __shared__ __align__(16) float sstat[8][32 * SST];   // 28 KB

    const int tid  = threadIdx.x;
    const int warp = tid >> 5;
    const int lane = tid & 31;
    const int sub  = lane >> 3;   // softmax group 0..3
    const int j    = lane & 7;    // lane within group

    float* sst = sstat[warp];
    const int row0 = (blockIdx.x * 8 + warp) * 32;

    // ---------------- Phase A: stats for 32 rows ----------------
    const float* cr = corners + (size_t)row0 * 132 + 33 * sub + j;
    const bool writer = (j == 0);

    #pragma unroll 1
    for (int i = 0; i < 32; i++, cr += 132) {
        if (row0 + i >= rows) break;

        float v0 = cr[0];
        float v1 = cr[8];
        float v2 = cr[16];
        float v3 = cr[24];
        float v4 = cr[32 - j];   // bin 32 (same addr for whole subgroup)

        // exp without max-subtraction: logits are O(1), fp32 has huge headroom
        float e0 = __expf(v0);
        float e1 = __expf(v1);
        float e2 = __expf(v2);
        float e3 = __expf(v3);
        float e4 = __expf(v4);
        float x  = writer ? e4 : 0.0f;   // count bin32 exactly once per group

        float s = (e0 + e1) + (e2 + e3) + x;
        s += __shfl_xor_sync(FULL, s, 1);
        s += __shfl_xor_sync(FULL, s, 2);
        s += __shfl_xor_sync(FULL, s, 4);

        // sort e0..e3 descending (5 CE)
        ce(e0, e1); ce(e2, e3); ce(e0, e2); ce(e1, e3); ce(e1, e2);
        // insert x (0 for non-writer lanes -> no-op)
        float c;
        float t0 = fmaxf(e0, x); c = fminf(e0, x);
        float t1 = fmaxf(e1, c); c = fminf(e1, c);
        float t2 = fmaxf(e2, c); c = fminf(e2, c);
        float t3 = fmaxf(e3, c);

        // butterfly merge of sorted quads across the 8-lane subgroup
        #pragma unroll
        for (int off = 1; off <= 4; off <<= 1) {
            float o0 = __shfl_xor_sync(FULL, t0, off);
            float o1 = __shfl_xor_sync(FULL, t1, off);
            float o2 = __shfl_xor_sync(FULL, t2, off);
            float o3 = __shfl_xor_sync(FULL, t3, off);
            float u0 = fmaxf(t0, o3);
            float u1 = fmaxf(t1, o2);
            float u2 = fmaxf(t2, o1);
            float u3 = fmaxf(t3, o0);
            ce(u0, u2); ce(u1, u3); ce(u0, u1); ce(u2, u3);
            t0 = u0; t1 = u1; t2 = u2; t3 = u3;
        }

        float inv = __frcp_rn(s);
        float p0 = t0 * inv;
        float p1 = t1 * inv;
        float p2 = t2 * inv;
        float p3 = t3 * inv;
        float mean = 0.25f * ((p0 + p1) + (p2 + p3));

        if (writer) {
            *(float4*)&sst[i * SST + 4 * sub] = make_float4(p0, p1, p2, p3);
            sst[i * SST + 16 + sub] = mean;
        }
    }
    __syncwarp();

    // ---------------- Phase B: MLP, lane = local row ----------------
    // stat layout in smem: [r*SST + 4g + t] = p_{g,t}, [r*SST + 16 + g] = mean_g
    float st[20];
    {
        float4 a0 = *(const float4*)&sst[lane * SST + 0];
        float4 a1 = *(const float4*)&sst[lane * SST + 4];
        float4 a2 = *(const float4*)&sst[lane * SST + 8];
        float4 a3 = *(const float4*)&sst[lane * SST + 12];
        float4 a4 = *(const float4*)&sst[lane * SST + 16];
        st[0] = a0.x; st[1] = a0.y; st[2]  = a0.z; st[3]  = a0.w; st[4]  = a4.x;
        st[5] = a1.x; st[6] = a1.y; st[7]  = a1.z; st[8]  = a1.w; st[9]  = a4.y;
        st[10]= a2.x; st[11]= a2.y; st[12] = a2.z; st[13] = a2.w; st[14] = a4.z;
        st[15]= a3.x; st[16]= a3.y; st[17] = a3.z; st[18] = a3.w; st[19] = a4.w;
    }
    float q = cb2[0];
    #pragma unroll
    for (int h = 0; h < 64; h++) {
        float acc = cb1[h];
        #pragma unroll
        for (int d = 0; d < 20; d++)
            acc += st[d] * cW1[d * 64 + h];
        q += fmaxf(acc, 0.0f) * cW2[h];
    }

    // ---------------- Phase C: output 32 rows ----------------
    const float4* s4 = (const float4*)(scores + (size_t)row0 * 80);
    float4*       o4 = (float4*)(out + (size_t)row0 * 80);
    #pragma unroll 1
    for (int i = 0; i < 32; i++) {
        float qb = __shfl_sync(FULL, q, i);
        if (row0 + i < rows && lane < 20) {
            float4 v = s4[i * 20 + lane];
            v.x += qb; v.y += qb; v.z += qb; v.w += qb;
            o4[i * 20 + lane] = v;
        }
    }
}

extern "C" void kernel_launch(void* const* d_in, const int* in_sizes, int n_in,
                              void* d_out, int out_size) {
    const float* scores  = (const float*)d_in[0];
    const float* corners = (const float*)d_in[1];

    cudaMemcpyToSymbolAsync(cW1, d_in[2], 20 * 64 * sizeof(float), 0,
                            cudaMemcpyDeviceToDevice, 0);
    cudaMemcpyToSymbolAsync(cb1, d_in[3], 64 * sizeof(float), 0,
                            cudaMemcpyDeviceToDevice, 0);
    cudaMemcpyToSymbolAsync(cW2, d_in[4], 64 * sizeof(float), 0,
                            cudaMemcpyDeviceToDevice, 0);
    cudaMemcpyToSymbolAsync(cb2, d_in[5], sizeof(float), 0,
                            cudaMemcpyDeviceToDevice, 0);

    float* out = (float*)d_out;
    int rows = in_sizes[0] / 80;             // B*L
    int blocks = (rows + 255) / 256;         // 8 warps/block, 32 rows/warp
    lqe_kernel<<<blocks, 256>>>(scores, corners, out, rows);
}

// round 8
// speedup vs baseline: 2.1735x; 2.1735x over previous
#include <cuda_runtime.h>

#define FULL 0xFFFFFFFFu

// Insert e into sorted (desc) top-4 registers t0>=t1>=t2>=t3.
__device__ __forceinline__ void ins4(float e, float& t0, float& t1, float& t2, float& t3)
{
    float c = e;
    float n0 = fmaxf(t0, c); c = fminf(t0, c);
    float n1 = fmaxf(t1, c); c = fminf(t1, c);
    float n2 = fmaxf(t2, c); c = fminf(t2, c);
    t3 = fmaxf(t3, c);
    t0 = n0; t1 = n1; t2 = n2;
}

// expf + accumulate + insert
__device__ __forceinline__ void acc_one(float v, float& s,
                                        float& t0, float& t1, float& t2, float& t3)
{
    float e = __expf(v);
    s += e;
    ins4(e, t0, t1, t2, t3);
}

// Block = 128 threads (4 warps) = 64 rows.
//  Phase A: thread (row=tid/2, half=tid&1) -> softmax-free top4+sum for 2 groups,
//           stats written in place into this lane's own consumed corner region.
//  Phase B: warp w: rows (w&1)*32 + lane, hidden half (w>>1). Uniform smem weights.
//  Phase C: flat coalesced float4 add of quality into scores.
__global__ __launch_bounds__(128)
void lqe_kernel(const float* __restrict__ scores,
                const float* __restrict__ corners,
                const float* __restrict__ gW1,
                const float* __restrict__ gb1,
                const float* __restrict__ gW2,
                const float* __restrict__ gb2,
                float* __restrict__ out,
                int rows)
{
    __shared__ __align__(16) float sC[64 * 132];   // 33792 B, pitch 132 floats
    __shared__ __align__(16) float sW1[20 * 64];   // 5120 B
    __shared__ __align__(16) float sB1[64];
    __shared__ __align__(16) float sW2[64];
    __shared__ float sQ0[64];
    __shared__ float sQ1[64];
    __shared__ float sB2;

    const int tid  = threadIdx.x;
    const int row0 = blockIdx.x * 64;
    const int nr   = min(64, rows - row0);

    // ---------------- stage corners (coalesced float4) ----------------
    {
        const float4* src = (const float4*)(corners + (size_t)row0 * 132);
        float4* dst = (float4*)sC;
        if (nr == 64) {                       // 2112 float4 = 16.5 * 128
            #pragma unroll
            for (int j = 0; j < 16; j++) dst[j * 128 + tid] = src[j * 128 + tid];
            if (tid < 64) dst[2048 + tid] = src[2048 + tid];
        } else {
            int n4 = nr * 33;
            for (int i = tid; i < n4; i += 128) dst[i] = src[i];
        }
    }
    // ---------------- stage weights ----------------
    {
        const float4* w4 = (const float4*)gW1;
        float4* d4 = (float4*)sW1;
        #pragma unroll
        for (int j = 0; j < 3; j++) {
            int idx = j * 128 + tid;
            if (idx < 320) d4[idx] = w4[idx];
        }
        if (tid < 64)  { sB1[tid] = gb1[tid]; sW2[tid] = gW2[tid]; }
        if (tid == 0)  { sB2 = gb2[0]; }
    }
    __syncthreads();

    // ---------------- Phase A ----------------
    const int lrow = tid >> 1;
    const int half = tid & 1;
    if (lrow < nr) {
        const float* base = sC + lrow * 132 + half * 66;
        // group X = base[0..32], group Y = base[33..65]
        float sx = 0.f, sy = 0.f;
        float x0 = 0.f, x1 = 0.f, x2 = 0.f, x3 = 0.f;
        float y0 = 0.f, y1 = 0.f, y2 = 0.f, y3 = 0.f;

        #pragma unroll
        for (int j = 0; j < 16; j++) {
            float2 a = *(const float2*)(base + 2 * j);        // X: 2j, 2j+1
            float2 b = *(const float2*)(base + 34 + 2 * j);   // Y: 34+2j, 35+2j
            acc_one(a.x, sx, x0, x1, x2, x3);
            acc_one(b.x, sy, y0, y1, y2, y3);
            acc_one(a.y, sx, x0, x1, x2, x3);
            acc_one(b.y, sy, y0, y1, y2, y3);
        }
        acc_one(base[32], sx, x0, x1, x2, x3);   // X tail
        acc_one(base[33], sy, y0, y1, y2, y3);   // Y tail

        float invx = __frcp_rn(sx);
        float invy = __frcp_rn(sy);
        float p0 = x0 * invx, p1 = x1 * invx, p2 = x2 * invx, p3 = x3 * invx;
        float q0 = y0 * invy, q1 = y1 * invy, q2 = y2 * invy, q3 = y3 * invy;
        float mx = 0.25f * ((p0 + p1) + (p2 + p3));
        float my = 0.25f * ((q0 + q1) + (q2 + q3));

        // stats in place over this lane's own (fully consumed) corner region:
        // half 0 -> sC[row*132 + 0..9], half 1 -> sC[row*132 + 68..77]
        float* so = sC + lrow * 132 + 68 * half;
        *(float2*)(so + 0) = make_float2(p0, p1);
        *(float2*)(so + 2) = make_float2(p2, p3);
        *(float2*)(so + 4) = make_float2(mx, q0);
        *(float2*)(so + 6) = make_float2(q1, q2);
        *(float2*)(so + 8) = make_float2(q3, my);
    }
    __syncthreads();

    // ---------------- Phase B: MLP ----------------
    {
        const int warp  = tid >> 5;
        const int lane  = tid & 31;
        const int mrow  = (warp & 1) * 32 + lane;   // row this lane computes
        const int kb    = (warp >> 1) * 32;          // hidden-half base: 0 or 32

        float st[20];
        {
            const float* sr = sC + mrow * 132;
            float4 a0 = *(const float4*)(sr + 0);
            float4 a1 = *(const float4*)(sr + 4);
            float4 a2 = *(const float4*)(sr + 8);    // .z,.w garbage (unused)
            float4 c0 = *(const float4*)(sr + 68);
            float4 c1 = *(const float4*)(sr + 72);
            float4 c2 = *(const float4*)(sr + 76);
            st[0]  = a0.x; st[1]  = a0.y; st[2]  = a0.z; st[3]  = a0.w;
            st[4]  = a1.x; st[5]  = a1.y; st[6]  = a1.z; st[7]  = a1.w;
            st[8]  = a2.x; st[9]  = a2.y;
            st[10] = c0.x; st[11] = c0.y; st[12] = c0.z; st[13] = c0.w;
            st[14] = c1.x; st[15] = c1.y; st[16] = c1.z; st[17] = c1.w;
            st[18] = c2.x; st[19] = c2.y;
        }

        float q = (kb == 0) ? sB2 : 0.f;
        #pragma unroll
        for (int pass = 0; pass < 2; pass++) {
            const int k0 = kb + pass * 16;
            float acc[16];
            #pragma unroll
            for (int kk = 0; kk < 16; kk += 4) {
                float4 b = *(const float4*)(sB1 + k0 + kk);
                acc[kk] = b.x; acc[kk + 1] = b.y; acc[kk + 2] = b.z; acc[kk + 3] = b.w;
            }
            #pragma unroll
            for (int d = 0; d < 20; d++) {
                float sd = st[d];
                const float4* wr = (const float4*)(sW1 + d * 64 + k0);
                #pragma unroll
                for (int kk = 0; kk < 4; kk++) {
                    float4 w = wr[kk];
                    acc[4 * kk + 0] += sd * w.x;
                    acc[4 * kk + 1] += sd * w.y;
                    acc[4 * kk + 2] += sd * w.z;
                    acc[4 * kk + 3] += sd * w.w;
                }
            }
            #pragma unroll
            for (int kk = 0; kk < 16; kk += 4) {
                float4 w2 = *(const float4*)(sW2 + k0 + kk);
                q += fmaxf(acc[kk + 0], 0.f) * w2.x;
                q += fmaxf(acc[kk + 1], 0.f) * w2.y;
                q += fmaxf(acc[kk + 2], 0.f) * w2.z;
                q += fmaxf(acc[kk + 3], 0.f) * w2.w;
            }
        }
        if (kb == 0) sQ0[mrow] = q; else sQ1[mrow] = q;
    }
    __syncthreads();

    // ---------------- Phase C: out = scores + q ----------------
    {
        const float4* s4 = (const float4*)(scores + (size_t)row0 * 80);
        float4*       o4 = (float4*)(out + (size_t)row0 * 80);
        if (nr == 64) {                       // 1280 float4 = 10 * 128
            #pragma unroll
            for (int j = 0; j < 10; j++) {
                int i = j * 128 + tid;
                int r = i / 20;
                float qv = sQ0[r] + sQ1[r];
                float4 v = s4[i];
                v.x += qv; v.y += qv; v.z += qv; v.w += qv;
                o4[i] = v;
            }
        } else {
            int n4 = nr * 20;
            for (int i = tid; i < n4; i += 128) {
                int r = i / 20;
                float qv = sQ0[r] + sQ1[r];
                float4 v = s4[i];
                v.x += qv; v.y += qv; v.z += qv; v.w += qv;
                o4[i] = v;
            }
        }
    }
}

extern "C" void kernel_launch(void* const* d_in, const int* in_sizes, int n_in,
                              void* d_out, int out_size) {
    const float* scores  = (const float*)d_in[0];
    const float* corners = (const float*)d_in[1];
    const float* W1      = (const float*)d_in[2];
    const float* b1      = (const float*)d_in[3];
    const float* W2      = (const float*)d_in[4];
    const float* b2      = (const float*)d_in[5];
    float* out = (float*)d_out;

    int rows = in_sizes[0] / 80;              // B*L
    int blocks = (rows + 63) / 64;
    lqe_kernel<<<blocks, 128>>>(scores, corners, W1, b1, W2, b2, out, rows);
}

// round 10
// speedup vs baseline: 2.3198x; 1.0673x over previous
#include <cuda_runtime.h>

// Insert e into sorted (desc) top-4 registers t0>=t1>=t2>=t3.
__device__ __forceinline__ void ins4(float e, float& t0, float& t1, float& t2, float& t3)
{
    float c = e;
    float n0 = fmaxf(t0, c); c = fminf(t0, c);
    float n1 = fmaxf(t1, c); c = fminf(t1, c);
    float n2 = fmaxf(t2, c); c = fminf(t2, c);
    t3 = fmaxf(t3, c);
    t0 = n0; t1 = n1; t2 = n2;
}

__device__ __forceinline__ void acc_one(float v, float& s,
                                        float& t0, float& t1, float& t2, float& t3)
{
    float e = __expf(v);
    s += e;
    ins4(e, t0, t1, t2, t3);
}

// Block = 128 threads (4 warps) = 32 rows.
//  Phase A: thread (row=tid>>2, g=tid&3): softmax-free top4+sum for ONE group of 33.
//           LDS bank = (4r+g+k) mod 32 -> conflict-free. Stats -> sStat pitch 21.
//  Phase B: warp w computes hidden units [16w,16w+16) for row=lane (2 passes of 8).
//  Phase C: coalesced float4: out = scores + sum of 4 partials + b2.
__global__ __launch_bounds__(128, 8)
void lqe_kernel(const float* __restrict__ scores,
                const float* __restrict__ corners,
                const float* __restrict__ gW1,
                const float* __restrict__ gb1,
                const float* __restrict__ gW2,
                const float* __restrict__ gb2,
                float* __restrict__ out,
                int rows)
{
    __shared__ __align__(16) float sC[32 * 132];     // 16896 B
    __shared__ __align__(16) float sW1[20 * 64];     //  5120 B
    __shared__ __align__(16) float sB1[64];
    __shared__ __align__(16) float sW2[64];
    __shared__ __align__(16) float sStat[32 * 21];   //  2688 B, pitch 21 (coprime 32)
    __shared__ float sQp[4 * 32];                    // per-warp partial q
    __shared__ float sB2;

    const int tid  = threadIdx.x;
    const int row0 = blockIdx.x * 32;
    const int nr   = min(32, rows - row0);

    // ---------------- stage corners (coalesced float4) ----------------
    {
        const float4* src = (const float4*)(corners + (size_t)row0 * 132);
        float4* dst = (float4*)sC;
        if (nr == 32) {                       // 1056 float4 = 8.25 * 128
            #pragma unroll
            for (int j = 0; j < 8; j++) dst[j * 128 + tid] = src[j * 128 + tid];
            if (tid < 32) dst[1024 + tid] = src[1024 + tid];
        } else {
            int n4 = nr * 33;
            for (int i = tid; i < n4; i += 128) dst[i] = src[i];
        }
    }
    // ---------------- stage weights ----------------
    {
        const float4* w4 = (const float4*)gW1;
        float4* d4 = (float4*)sW1;
        #pragma unroll
        for (int j = 0; j < 3; j++) {
            int idx = j * 128 + tid;
            if (idx < 320) d4[idx] = w4[idx];
        }
        if (tid < 64)       sB1[tid] = gb1[tid];
        else if (tid < 128) sW2[tid - 64] = gW2[tid - 64];
        if (tid == 0)       sB2 = gb2[0];
    }
    __syncthreads();

    // ---------------- Phase A: one group of 33 per thread ----------------
    {
        const int lrow = tid >> 2;
        const int g    = tid & 3;
        if (lrow < nr) {
            const float* base = sC + lrow * 132 + 33 * g;
            float s = 0.f;
            float t0 = 0.f, t1 = 0.f, t2 = 0.f, t3 = 0.f;
            #pragma unroll
            for (int k = 0; k < 33; k++)
                acc_one(base[k], s, t0, t1, t2, t3);

            float inv = __frcp_rn(s);
            float p0 = t0 * inv, p1 = t1 * inv, p2 = t2 * inv, p3 = t3 * inv;
            float mean = 0.25f * ((p0 + p1) + (p2 + p3));

            float* so = sStat + lrow * 21 + 5 * g;
            so[0] = p0; so[1] = p1; so[2] = p2; so[3] = p3; so[4] = mean;
        }
    }
    __syncthreads();

    // ---------------- Phase B: MLP (warp w -> hidden [16w,16w+16), row=lane) ----------------
    {
        const int warp = tid >> 5;
        const int lane = tid & 31;

        float st[20];
        {
            const float* sr = sStat + lane * 21;   // bank = 21*lane + d: conflict-free
            #pragma unroll
            for (int d = 0; d < 20; d++) st[d] = sr[d];
        }

        float q = 0.f;
        #pragma unroll
        for (int pass = 0; pass < 2; pass++) {
            const int h0 = warp * 16 + pass * 8;
            float acc[8];
            {
                float4 ba = *(const float4*)(sB1 + h0);
                float4 bb = *(const float4*)(sB1 + h0 + 4);
                acc[0] = ba.x; acc[1] = ba.y; acc[2] = ba.z; acc[3] = ba.w;
                acc[4] = bb.x; acc[5] = bb.y; acc[6] = bb.z; acc[7] = bb.w;
            }
            #pragma unroll
            for (int d = 0; d < 20; d++) {
                float sd = st[d];
                float4 wa = *(const float4*)(sW1 + d * 64 + h0);      // uniform -> broadcast
                float4 wb = *(const float4*)(sW1 + d * 64 + h0 + 4);
                acc[0] += sd * wa.x; acc[1] += sd * wa.y;
                acc[2] += sd * wa.z; acc[3] += sd * wa.w;
                acc[4] += sd * wb.x; acc[5] += sd * wb.y;
                acc[6] += sd * wb.z; acc[7] += sd * wb.w;
            }
            {
                float4 wa = *(const float4*)(sW2 + h0);
                float4 wb = *(const float4*)(sW2 + h0 + 4);
                q += fmaxf(acc[0], 0.f) * wa.x;
                q += fmaxf(acc[1], 0.f) * wa.y;
                q += fmaxf(acc[2], 0.f) * wa.z;
                q += fmaxf(acc[3], 0.f) * wa.w;
                q += fmaxf(acc[4], 0.f) * wb.x;
                q += fmaxf(acc[5], 0.f) * wb.y;
                q += fmaxf(acc[6], 0.f) * wb.z;
                q += fmaxf(acc[7], 0.f) * wb.w;
            }
        }
        sQp[warp * 32 + lane] = q;
    }
    __syncthreads();

    // ---------------- Phase C: out = scores + q ----------------
    {
        const float4* s4 = (const float4*)(scores + (size_t)row0 * 80);
        float4*       o4 = (float4*)(out + (size_t)row0 * 80);
        if (nr == 32) {                       // 640 float4 = 5 * 128
            #pragma unroll
            for (int j = 0; j < 5; j++) {
                int i = j * 128 + tid;
                int r = i / 20;
                float qv = (sQp[r] + sQp[32 + r]) + (sQp[64 + r] + sQp[96 + r]) + sB2;
                float4 v = s4[i];
                v.x += qv; v.y += qv; v.z += qv; v.w += qv;
                o4[i] = v;
            }
        } else {
            int n4 = nr * 20;
            for (int i = tid; i < n4; i += 128) {
                int r = i / 20;
                float qv = (sQp[r] + sQp[32 + r]) + (sQp[64 + r] + sQp[96 + r]) + sB2;
                float4 v = s4[i];
                v.x += qv; v.y += qv; v.z += qv; v.w += qv;
                o4[i] = v;
            }
        }
    }
}

extern "C" void kernel_launch(void* const* d_in, const int* in_sizes, int n_in,
                              void* d_out, int out_size) {
    const float* scores  = (const float*)d_in[0];
    const float* corners = (const float*)d_in[1];
    const float* W1      = (const float*)d_in[2];
    const float* b1      = (const float*)d_in[3];
    const float* W2      = (const float*)d_in[4];
    const float* b2      = (const float*)d_in[5];
    float* out = (float*)d_out;

    int rows = in_sizes[0] / 80;              // B*L
    int blocks = (rows + 31) / 32;
    lqe_kernel<<<blocks, 128>>>(scores, corners, W1, b1, W2, b2, out, rows);
}